// round 11
// baseline (speedup 1.0000x reference)
#include <cuda_runtime.h>
#include <cuda_fp16.h>
#include <cstdint>

// ---------------------------------------------------------------------------
// Problem constants
// ---------------------------------------------------------------------------
#define K_DIM 4096
#define N_DIM 11008
#define M_DIM 8192
#define NGC   (N_DIM / 8)          // packed int32 per K row

// GEMM tiling
#define BM 128
#define BN 128
#define BK 64
#define KT (K_DIM / BK)            // 64 k-iterations
#define NSTAGES 3
#define STAGE_A_BYTES (BM * BK * 2)    // 16384
#define STAGE_B_BYTES (BN * BK * 2)    // 16384
#define SMEM_A 0
#define SMEM_B (NSTAGES * STAGE_A_BYTES)                  // 49152
#define SMEM_COEF (SMEM_B + NSTAGES * STAGE_B_BYTES)      // 98304
#define SMEM_TOTAL (SMEM_COEF + 3 * BN * 4)               // 99840

#define NT_TILES (N_DIM / BN)      // 86
#define MT_TILES (M_DIM / BM)      // 64
#define GROUP_M 8

#define UNPACK_BLOCKS ((N_DIM / 256) * (K_DIM / 64))   // 43 * 64 = 2752
#define NB_BLOCKS (N_DIM / 256)                        // 43

// ---------------------------------------------------------------------------
// Device scratch (no allocations allowed in kernel_launch)
// ---------------------------------------------------------------------------
__device__ __align__(1024) __half g_Wt[(size_t)N_DIM * K_DIM];   // W^T [N,K] fp16
__device__ __align__(1024) __half g_Xh[(size_t)M_DIM * K_DIM];   // X   [M,K] fp16
__device__ float g_rowsum[M_DIM];

// ---------------------------------------------------------------------------
// PTX helpers (generic sm_80-level PTX only: compiles under compute_103)
// ---------------------------------------------------------------------------
__device__ __forceinline__ uint32_t smem_u32(const void* p) {
    uint32_t a;
    asm("{ .reg .u64 t; cvta.to.shared.u64 t, %1; cvt.u32.u64 %0, t; }"
        : "=r"(a) : "l"(p));
    return a;
}

__device__ __forceinline__ void cp_async16(uint32_t dst, const void* src) {
    asm volatile("cp.async.cg.shared.global [%0], [%1], 16;"
                 :: "r"(dst), "l"(__cvta_generic_to_global(src)) : "memory");
}
__device__ __forceinline__ void cp_commit() {
    asm volatile("cp.async.commit_group;" ::: "memory");
}
template <int N>
__device__ __forceinline__ void cp_wait() {
    asm volatile("cp.async.wait_group %0;" :: "n"(N) : "memory");
}

__device__ __forceinline__ void ldsm_x4(uint32_t& r0, uint32_t& r1, uint32_t& r2,
                                        uint32_t& r3, uint32_t addr) {
    asm volatile("ldmatrix.sync.aligned.m8n8.x4.shared.b16 {%0,%1,%2,%3}, [%4];"
                 : "=r"(r0), "=r"(r1), "=r"(r2), "=r"(r3) : "r"(addr));
}

__device__ __forceinline__ void mma16816(float* c, const uint32_t* a, const uint32_t* b) {
    asm volatile(
        "mma.sync.aligned.m16n8k16.row.col.f32.f16.f16.f32 "
        "{%0,%1,%2,%3}, {%4,%5,%6,%7}, {%8,%9}, {%0,%1,%2,%3};"
        : "+f"(c[0]), "+f"(c[1]), "+f"(c[2]), "+f"(c[3])
        : "r"(a[0]), "r"(a[1]), "r"(a[2]), "r"(a[3]), "r"(b[0]), "r"(b[1]));
}

// ---------------------------------------------------------------------------
// Kernel 0 (fused prep): blocks [0, UNPACK_BLOCKS) unpack int4 weights ->
// g_Wt[N][K] fp16; blocks [UNPACK_BLOCKS, +M_DIM) convert X fp32 -> fp16 +
// rowsum of the rounded values. Independent work, overlapped on the chip.
// ---------------------------------------------------------------------------
__global__ __launch_bounds__(256) void prep_kernel(const int* __restrict__ qw,
                                                   const float* __restrict__ x) {
    __shared__ int w[64][32];          // 8KB (unpack branch only)
    __shared__ float ws[8];

    if (blockIdx.x < UNPACK_BLOCKS) {
        const int bx = blockIdx.x % NB_BLOCKS;
        const int by = blockIdx.x / NB_BLOCKS;
        const int n0 = bx * 256;
        const int k0 = by * 64;
        const int ngBase = n0 >> 3;
        const int lane = threadIdx.x & 31;
        const int wq = threadIdx.x >> 5;

#pragma unroll
        for (int i = 0; i < 8; i++) {
            const int k = wq * 8 + i;
            w[k][lane] = qw[(size_t)(k0 + k) * NGC + ngBase + lane];
        }
        __syncthreads();

        const int t = threadIdx.x;     // owns output row n0 + t
        const int col = t >> 3;
        const int sh = (t & 7) * 4;
        __half2 buf[32];
#pragma unroll
        for (int k = 0; k < 64; k += 2) {
            const uint32_t q0 = ((uint32_t)w[k][col] >> sh) & 0xF;
            const uint32_t q1 = ((uint32_t)w[k + 1][col] >> sh) & 0xF;
            buf[k >> 1] = __floats2half2_rn((float)q0, (float)q1);
        }
        uint4* dst = reinterpret_cast<uint4*>(g_Wt + (size_t)(n0 + t) * K_DIM + k0);
        const uint4* src = reinterpret_cast<const uint4*>(buf);
#pragma unroll
        for (int i = 0; i < 8; i++) dst[i] = src[i];
    } else {
        const int m = blockIdx.x - UNPACK_BLOCKS;
        const float4* xr = reinterpret_cast<const float4*>(x + (size_t)m * K_DIM);
        uint2* xo = reinterpret_cast<uint2*>(g_Xh + (size_t)m * K_DIM);
        float sum = 0.f;
#pragma unroll
        for (int i = 0; i < 4; i++) {
            const int j = threadIdx.x + i * 256;
            const float4 v = xr[j];
            __half2 a = __floats2half2_rn(v.x, v.y);
            __half2 b = __floats2half2_rn(v.z, v.w);
            uint2 u;
            u.x = *reinterpret_cast<uint32_t*>(&a);
            u.y = *reinterpret_cast<uint32_t*>(&b);
            xo[j] = u;
            const float2 fa = __half22float2(a);
            const float2 fb = __half22float2(b);
            sum += (fa.x + fa.y) + (fb.x + fb.y);
        }
#pragma unroll
        for (int off = 16; off; off >>= 1) sum += __shfl_xor_sync(0xffffffffu, sum, off);
        if ((threadIdx.x & 31) == 0) ws[threadIdx.x >> 5] = sum;
        __syncthreads();
        if (threadIdx.x == 0) {
            float s = 0.f;
#pragma unroll
            for (int wi = 0; wi < 8; wi++) s += ws[wi];
            g_rowsum[m] = s;
        }
    }
}

// ---------------------------------------------------------------------------
// Kernel 1: mma.sync fp16 GEMM, 128x128x64 CTA tile, four 64x64 warps, occ 2,
// 3-stage cp.async pipeline, one barrier per k-iter, persistent fragment
// double-buffer with tail prefetch; the refill LDGSTS burst is issued AFTER
// the first ks MMA block so post-barrier issue slots go straight to HMMA.
// Epilogue: out = acc*scale - rowsum*scale*zp + bias
// ---------------------------------------------------------------------------
__global__ __launch_bounds__(128, 2) void gemm_kernel(
    const float* __restrict__ scales,
    const int*   __restrict__ qzeros,
    const float* __restrict__ bias,
    float* __restrict__ out)
{
    extern __shared__ char smem[];
    const uint32_t sb = smem_u32(smem);
    const int tid = threadIdx.x;
    const int lane = tid & 31;
    const int wid = tid >> 5;           // 0..3

    // CTA swizzle: GROUP_M m-tiles per group for L2 reuse
    const int pid = blockIdx.x;
    const int group = pid / (GROUP_M * NT_TILES);
    const int rem = pid - group * (GROUP_M * NT_TILES);
    const int mt = group * GROUP_M + (rem & (GROUP_M - 1));
    const int nt = rem >> 3;   // GROUP_M == 8
    const int mBase = mt * BM;
    const int nBase = nt * BN;

    // Epilogue coefficients (128 threads cover BN=128 exactly)
    float* sS = reinterpret_cast<float*>(smem + SMEM_COEF);
    float* sZ = sS + BN;
    float* sBi = sZ + BN;
    {
        const int n = nBase + tid;
        const float sc = scales[n];
        const int zq = qzeros[n >> 3];
        const int zp = (zq >> ((n & 7) * 4)) & 0xF;
        sS[tid] = sc;
        sZ[tid] = sc * (float)zp;
        sBi[tid] = bias[n];
    }

    // cp.async indices: 128 threads, 16B chunks; rows of 128B (8 chunks)
    const int ldRow = tid >> 3;          // 0..15
    const int ldChunk = tid & 7;         // 0..7
    const uint32_t swz = (uint32_t)((ldChunk ^ (ldRow & 7)) << 4);

    const __half* gA = g_Xh + (size_t)mBase * K_DIM;
    const __half* gB = g_Wt + (size_t)nBase * K_DIM;

    auto issue = [&](int st, int kt) {
        const int gk = kt * BK + ldChunk * 8;
#pragma unroll
        for (int i = 0; i < 8; i++) {
            const int row = ldRow + i * 16;
            cp_async16(sb + SMEM_A + st * STAGE_A_BYTES + row * 128 + swz,
                       gA + (size_t)row * K_DIM + gk);
        }
#pragma unroll
        for (int i = 0; i < 8; i++) {
            const int row = ldRow + i * 16;
            cp_async16(sb + SMEM_B + st * STAGE_B_BYTES + row * 128 + swz,
                       gB + (size_t)row * K_DIM + gk);
        }
    };

    // Warp tiling: 2 (m) x 2 (n) warps; warp tile 64 x 64
    const int warp_m = wid >> 1;         // 0..1
    const int warp_n = wid & 1;          // 0..1
    const int rowA0 = warp_m * 64 + (lane & 15);
    const int rowB0 = warp_n * 64 + (lane & 15);
    const int halfSel = lane >> 4;

    const uint32_t aAddrBase = sb + SMEM_A + rowA0 * 128;
    const uint32_t bAddrBase = sb + SMEM_B + rowB0 * 128;
    const uint32_t xorA = (uint32_t)(rowA0 & 7);
    const uint32_t xorB = (uint32_t)(rowB0 & 7);

    float acc[4][8][4];
#pragma unroll
    for (int mi = 0; mi < 4; mi++)
#pragma unroll
        for (int nj = 0; nj < 8; nj++)
#pragma unroll
            for (int e = 0; e < 4; e++) acc[mi][nj][e] = 0.f;

    uint32_t afr[2][4][4];
    uint32_t bfr[2][8][2];

    // Fragment loader: stage base addresses + k16 slice ks -> buffer buf
    auto loadFrag = [&](int buf, uint32_t aSt, uint32_t bSt, int ks) {
        const uint32_t c = (uint32_t)(ks * 2 + halfSel);
#pragma unroll
        for (int mi = 0; mi < 4; mi++) {
            ldsm_x4(afr[buf][mi][0], afr[buf][mi][1], afr[buf][mi][2],
                    afr[buf][mi][3], aSt + mi * 16 * 128 + ((c ^ xorA) << 4));
        }
#pragma unroll
        for (int ni = 0; ni < 4; ni++) {
            uint32_t r0, r1, r2, r3;
            ldsm_x4(r0, r1, r2, r3, bSt + ni * 16 * 128 + ((c ^ xorB) << 4));
            bfr[buf][ni * 2][0] = r0;     bfr[buf][ni * 2][1] = r2;
            bfr[buf][ni * 2 + 1][0] = r1; bfr[buf][ni * 2 + 1][1] = r3;
        }
    };

    // Prologue: fill stages 0 and 1; preload (kt=0, ks=0) fragments
    issue(0, 0); cp_commit();
    issue(1, 1); cp_commit();
    cp_wait<1>();
    __syncthreads();
    loadFrag(0, aAddrBase, bAddrBase, 0);

    int stRead = 0;                      // stage holding k-iter kt
    int stWrite = NSTAGES - 1;           // stage to refill (= (kt+2)%3)

    for (int kt = 0; kt < KT; kt++) {
        __syncthreads();                 // all warps done reading stage stWrite

        const uint32_t aSt = aAddrBase + stRead * STAGE_A_BYTES;
        const uint32_t bSt = bAddrBase + stRead * STAGE_B_BYTES;
        const int stNext = (stRead == NSTAGES - 1) ? 0 : stRead + 1;
        const uint32_t aNx = aAddrBase + stNext * STAGE_A_BYTES;
        const uint32_t bNx = bAddrBase + stNext * STAGE_B_BYTES;

        // ks = 0: fragments already in registers (tail prefetch) -> pure HMMA
        loadFrag(1, aSt, bSt, 1);
#pragma unroll
        for (int mi = 0; mi < 4; mi++)
#pragma unroll
            for (int nj = 0; nj < 8; nj++)
                mma16816(acc[mi][nj], afr[0][mi], bfr[0][nj]);

        // Refill burst AFTER the first MMA block (3-stage slack absorbs it)
        const int pf = kt + 2;
        if (pf < KT) issue(stWrite, pf);
        cp_commit();

#pragma unroll
        for (int ks = 1; ks < 4; ks++) {
            const int cb = ks & 1;
            if (ks < 3) {
                loadFrag(cb ^ 1, aSt, bSt, ks + 1);
            } else if (kt + 1 < KT) {
                // Tail prefetch: kt+1's stage resident after wait<1>
                cp_wait<1>();
                loadFrag(cb ^ 1, aNx, bNx, 0);
            }
#pragma unroll
            for (int mi = 0; mi < 4; mi++)
#pragma unroll
                for (int nj = 0; nj < 8; nj++)
                    mma16816(acc[mi][nj], afr[cb][mi], bfr[cb][nj]);
        }

        stRead = stNext;
        stWrite = (stWrite == NSTAGES - 1) ? 0 : stWrite + 1;
    }
    cp_wait<0>();

    // ---- Epilogue ----
    const int groupRow = lane >> 2;
    const int colPair = (lane & 3) * 2;
#pragma unroll
    for (int mi = 0; mi < 4; mi++) {
        const int r0 = mBase + warp_m * 64 + mi * 16 + groupRow;
        const int r1 = r0 + 8;
        const float rs0 = g_rowsum[r0];
        const float rs1 = g_rowsum[r1];
        float* o0 = out + (size_t)r0 * N_DIM + nBase;
        float* o1 = out + (size_t)r1 * N_DIM + nBase;
#pragma unroll
        for (int nj = 0; nj < 8; nj++) {
            const int c = warp_n * 64 + nj * 8 + colPair;
            float2 v0, v1;
            v0.x = acc[mi][nj][0] * sS[c]     - rs0 * sZ[c]     + sBi[c];
            v0.y = acc[mi][nj][1] * sS[c + 1] - rs0 * sZ[c + 1] + sBi[c + 1];
            v1.x = acc[mi][nj][2] * sS[c]     - rs1 * sZ[c]     + sBi[c];
            v1.y = acc[mi][nj][3] * sS[c + 1] - rs1 * sZ[c + 1] + sBi[c + 1];
            *reinterpret_cast<float2*>(o0 + c) = v0;
            *reinterpret_cast<float2*>(o1 + c) = v1;
        }
    }
}

// ---------------------------------------------------------------------------
// Host
// ---------------------------------------------------------------------------
extern "C" void kernel_launch(void* const* d_in, const int* in_sizes, int n_in,
                              void* d_out, int out_size) {
    const float* x       = (const float*)d_in[0];
    const int*   qweight = (const int*)d_in[1];
    const float* scales  = (const float*)d_in[2];
    const int*   qzeros  = (const int*)d_in[3];
    const float* bias    = (const float*)d_in[4];
    float* out = (float*)d_out;

    cudaFuncSetAttribute(gemm_kernel, cudaFuncAttributeMaxDynamicSharedMemorySize,
                         SMEM_TOTAL);

    prep_kernel<<<UNPACK_BLOCKS + M_DIM, 256>>>(qweight, x);
    gemm_kernel<<<MT_TILES * NT_TILES, 128, SMEM_TOTAL>>>(scales, qzeros, bias, out);
}

// round 12
// speedup vs baseline: 1.0091x; 1.0091x over previous
#include <cuda_runtime.h>
#include <cuda_fp16.h>
#include <cstdint>

// ---------------------------------------------------------------------------
// Problem constants
// ---------------------------------------------------------------------------
#define K_DIM 4096
#define N_DIM 11008
#define M_DIM 8192
#define NGC   (N_DIM / 8)          // packed int32 per K row

// GEMM tiling
#define BM 128
#define BN 128
#define BK 64
#define KT (K_DIM / BK)            // 64 k-iterations
#define NSTAGES 3
#define STAGE_A_BYTES (BM * BK * 2)    // 16384
#define STAGE_B_BYTES (BN * BK * 2)    // 16384
#define SMEM_A 0
#define SMEM_B (NSTAGES * STAGE_A_BYTES)                  // 49152
#define SMEM_COEF (SMEM_B + NSTAGES * STAGE_B_BYTES)      // 98304
#define SMEM_TOTAL (SMEM_COEF + 3 * BN * 4)               // 99840

#define NT_TILES (N_DIM / BN)      // 86
#define MT_TILES (M_DIM / BM)      // 64
#define GROUP_M 8

#define UNPACK_BLOCKS ((N_DIM / 256) * (K_DIM / 64))   // 43 * 64 = 2752
#define NB_BLOCKS (N_DIM / 256)                        // 43

// ---------------------------------------------------------------------------
// Device scratch (no allocations allowed in kernel_launch)
// ---------------------------------------------------------------------------
__device__ __align__(1024) __half g_Wt[(size_t)N_DIM * K_DIM];   // W^T [N,K] fp16
__device__ __align__(1024) __half g_Xh[(size_t)M_DIM * K_DIM];   // X   [M,K] fp16
__device__ float g_rowsum[M_DIM];

// ---------------------------------------------------------------------------
// PTX helpers (generic sm_80-level PTX only: compiles under compute_103)
// ---------------------------------------------------------------------------
__device__ __forceinline__ uint32_t smem_u32(const void* p) {
    uint32_t a;
    asm("{ .reg .u64 t; cvta.to.shared.u64 t, %1; cvt.u32.u64 %0, t; }"
        : "=r"(a) : "l"(p));
    return a;
}

__device__ __forceinline__ void cp_async16(uint32_t dst, const void* src) {
    asm volatile("cp.async.cg.shared.global [%0], [%1], 16;"
                 :: "r"(dst), "l"(__cvta_generic_to_global(src)) : "memory");
}
__device__ __forceinline__ void cp_commit() {
    asm volatile("cp.async.commit_group;" ::: "memory");
}
template <int N>
__device__ __forceinline__ void cp_wait() {
    asm volatile("cp.async.wait_group %0;" :: "n"(N) : "memory");
}

__device__ __forceinline__ void ldsm_x4(uint32_t& r0, uint32_t& r1, uint32_t& r2,
                                        uint32_t& r3, uint32_t addr) {
    asm volatile("ldmatrix.sync.aligned.m8n8.x4.shared.b16 {%0,%1,%2,%3}, [%4];"
                 : "=r"(r0), "=r"(r1), "=r"(r2), "=r"(r3) : "r"(addr));
}

__device__ __forceinline__ void mma16816(float* c, const uint32_t* a, const uint32_t* b) {
    asm volatile(
        "mma.sync.aligned.m16n8k16.row.col.f32.f16.f16.f32 "
        "{%0,%1,%2,%3}, {%4,%5,%6,%7}, {%8,%9}, {%0,%1,%2,%3};"
        : "+f"(c[0]), "+f"(c[1]), "+f"(c[2]), "+f"(c[3])
        : "r"(a[0]), "r"(a[1]), "r"(a[2]), "r"(a[3]), "r"(b[0]), "r"(b[1]));
}

// ---------------------------------------------------------------------------
// Kernel 0 (fused prep): blocks [0, UNPACK_BLOCKS) unpack int4 weights ->
// g_Wt[N][K] fp16; blocks [UNPACK_BLOCKS, +M_DIM) convert X fp32 -> fp16 +
// rowsum of the rounded values. Independent work, overlapped on the chip.
// ---------------------------------------------------------------------------
__global__ __launch_bounds__(256) void prep_kernel(const int* __restrict__ qw,
                                                   const float* __restrict__ x) {
    __shared__ int w[64][32];          // 8KB (unpack branch only)
    __shared__ float ws[8];

    if (blockIdx.x < UNPACK_BLOCKS) {
        const int bx = blockIdx.x % NB_BLOCKS;
        const int by = blockIdx.x / NB_BLOCKS;
        const int n0 = bx * 256;
        const int k0 = by * 64;
        const int ngBase = n0 >> 3;
        const int lane = threadIdx.x & 31;
        const int wq = threadIdx.x >> 5;

#pragma unroll
        for (int i = 0; i < 8; i++) {
            const int k = wq * 8 + i;
            w[k][lane] = qw[(size_t)(k0 + k) * NGC + ngBase + lane];
        }
        __syncthreads();

        const int t = threadIdx.x;     // owns output row n0 + t
        const int col = t >> 3;
        const int sh = (t & 7) * 4;
        __half2 buf[32];
#pragma unroll
        for (int k = 0; k < 64; k += 2) {
            const uint32_t q0 = ((uint32_t)w[k][col] >> sh) & 0xF;
            const uint32_t q1 = ((uint32_t)w[k + 1][col] >> sh) & 0xF;
            buf[k >> 1] = __floats2half2_rn((float)q0, (float)q1);
        }
        uint4* dst = reinterpret_cast<uint4*>(g_Wt + (size_t)(n0 + t) * K_DIM + k0);
        const uint4* src = reinterpret_cast<const uint4*>(buf);
#pragma unroll
        for (int i = 0; i < 8; i++) dst[i] = src[i];
    } else {
        const int m = blockIdx.x - UNPACK_BLOCKS;
        const float4* xr = reinterpret_cast<const float4*>(x + (size_t)m * K_DIM);
        uint2* xo = reinterpret_cast<uint2*>(g_Xh + (size_t)m * K_DIM);
        float sum = 0.f;
#pragma unroll
        for (int i = 0; i < 4; i++) {
            const int j = threadIdx.x + i * 256;
            const float4 v = xr[j];
            __half2 a = __floats2half2_rn(v.x, v.y);
            __half2 b = __floats2half2_rn(v.z, v.w);
            uint2 u;
            u.x = *reinterpret_cast<uint32_t*>(&a);
            u.y = *reinterpret_cast<uint32_t*>(&b);
            xo[j] = u;
            const float2 fa = __half22float2(a);
            const float2 fb = __half22float2(b);
            sum += (fa.x + fa.y) + (fb.x + fb.y);
        }
#pragma unroll
        for (int off = 16; off; off >>= 1) sum += __shfl_xor_sync(0xffffffffu, sum, off);
        if ((threadIdx.x & 31) == 0) ws[threadIdx.x >> 5] = sum;
        __syncthreads();
        if (threadIdx.x == 0) {
            float s = 0.f;
#pragma unroll
            for (int wi = 0; wi < 8; wi++) s += ws[wi];
            g_rowsum[m] = s;
        }
    }
}

// ---------------------------------------------------------------------------
// Kernel 1: mma.sync fp16 GEMM, 128x128x64 CTA tile, four 64x64 warps, occ 2,
// 3-stage cp.async pipeline, one barrier per k-iter, persistent fragment
// double-buffer with tail prefetch (round-10 mainloop ordering: refill burst
// issued right after the barrier; post-barrier MMAs use preloaded registers).
// Epilogue: out = acc*scale - rowsum*scale*zp + bias
// ---------------------------------------------------------------------------
__global__ __launch_bounds__(128, 2) void gemm_kernel(
    const float* __restrict__ scales,
    const int*   __restrict__ qzeros,
    const float* __restrict__ bias,
    float* __restrict__ out)
{
    extern __shared__ char smem[];
    const uint32_t sb = smem_u32(smem);
    const int tid = threadIdx.x;
    const int lane = tid & 31;
    const int wid = tid >> 5;           // 0..3

    // CTA swizzle: GROUP_M m-tiles per group for L2 reuse
    const int pid = blockIdx.x;
    const int group = pid / (GROUP_M * NT_TILES);
    const int rem = pid - group * (GROUP_M * NT_TILES);
    const int mt = group * GROUP_M + (rem & (GROUP_M - 1));
    const int nt = rem >> 3;   // GROUP_M == 8
    const int mBase = mt * BM;
    const int nBase = nt * BN;

    // Epilogue coefficients (128 threads cover BN=128 exactly)
    float* sS = reinterpret_cast<float*>(smem + SMEM_COEF);
    float* sZ = sS + BN;
    float* sBi = sZ + BN;
    {
        const int n = nBase + tid;
        const float sc = scales[n];
        const int zq = qzeros[n >> 3];
        const int zp = (zq >> ((n & 7) * 4)) & 0xF;
        sS[tid] = sc;
        sZ[tid] = sc * (float)zp;
        sBi[tid] = bias[n];
    }

    // cp.async indices: 128 threads, 16B chunks; rows of 128B (8 chunks)
    const int ldRow = tid >> 3;          // 0..15
    const int ldChunk = tid & 7;         // 0..7
    const uint32_t swz = (uint32_t)((ldChunk ^ (ldRow & 7)) << 4);

    const __half* gA = g_Xh + (size_t)mBase * K_DIM;
    const __half* gB = g_Wt + (size_t)nBase * K_DIM;

    auto issue = [&](int st, int kt) {
        const int gk = kt * BK + ldChunk * 8;
#pragma unroll
        for (int i = 0; i < 8; i++) {
            const int row = ldRow + i * 16;
            cp_async16(sb + SMEM_A + st * STAGE_A_BYTES + row * 128 + swz,
                       gA + (size_t)row * K_DIM + gk);
        }
#pragma unroll
        for (int i = 0; i < 8; i++) {
            const int row = ldRow + i * 16;
            cp_async16(sb + SMEM_B + st * STAGE_B_BYTES + row * 128 + swz,
                       gB + (size_t)row * K_DIM + gk);
        }
    };

    // Warp tiling: 2 (m) x 2 (n) warps; warp tile 64 x 64
    const int warp_m = wid >> 1;         // 0..1
    const int warp_n = wid & 1;          // 0..1
    const int rowA0 = warp_m * 64 + (lane & 15);
    const int rowB0 = warp_n * 64 + (lane & 15);
    const int halfSel = lane >> 4;

    const uint32_t aAddrBase = sb + SMEM_A + rowA0 * 128;
    const uint32_t bAddrBase = sb + SMEM_B + rowB0 * 128;
    const uint32_t xorA = (uint32_t)(rowA0 & 7);
    const uint32_t xorB = (uint32_t)(rowB0 & 7);

    float acc[4][8][4];
#pragma unroll
    for (int mi = 0; mi < 4; mi++)
#pragma unroll
        for (int nj = 0; nj < 8; nj++)
#pragma unroll
            for (int e = 0; e < 4; e++) acc[mi][nj][e] = 0.f;

    uint32_t afr[2][4][4];
    uint32_t bfr[2][8][2];

    // Fragment loader: stage base addresses + k16 slice ks -> buffer buf
    auto loadFrag = [&](int buf, uint32_t aSt, uint32_t bSt, int ks) {
        const uint32_t c = (uint32_t)(ks * 2 + halfSel);
#pragma unroll
        for (int mi = 0; mi < 4; mi++) {
            ldsm_x4(afr[buf][mi][0], afr[buf][mi][1], afr[buf][mi][2],
                    afr[buf][mi][3], aSt + mi * 16 * 128 + ((c ^ xorA) << 4));
        }
#pragma unroll
        for (int ni = 0; ni < 4; ni++) {
            uint32_t r0, r1, r2, r3;
            ldsm_x4(r0, r1, r2, r3, bSt + ni * 16 * 128 + ((c ^ xorB) << 4));
            bfr[buf][ni * 2][0] = r0;     bfr[buf][ni * 2][1] = r2;
            bfr[buf][ni * 2 + 1][0] = r1; bfr[buf][ni * 2 + 1][1] = r3;
        }
    };

    // Prologue: fill stages 0 and 1; preload (kt=0, ks=0) fragments
    issue(0, 0); cp_commit();
    issue(1, 1); cp_commit();
    cp_wait<1>();
    __syncthreads();
    loadFrag(0, aAddrBase, bAddrBase, 0);

    int stRead = 0;                      // stage holding k-iter kt
    int stWrite = NSTAGES - 1;           // stage to refill (= (kt+2)%3)

    for (int kt = 0; kt < KT; kt++) {
        __syncthreads();                 // all warps done reading stage stWrite

        const int pf = kt + 2;
        if (pf < KT) issue(stWrite, pf);
        cp_commit();

        const uint32_t aSt = aAddrBase + stRead * STAGE_A_BYTES;
        const uint32_t bSt = bAddrBase + stRead * STAGE_B_BYTES;
        const int stNext = (stRead == NSTAGES - 1) ? 0 : stRead + 1;
        const uint32_t aNx = aAddrBase + stNext * STAGE_A_BYTES;
        const uint32_t bNx = bAddrBase + stNext * STAGE_B_BYTES;

#pragma unroll
        for (int ks = 0; ks < 4; ks++) {
            const int cb = ks & 1;
            if (ks < 3) {
                loadFrag(cb ^ 1, aSt, bSt, ks + 1);
            } else if (kt + 1 < KT) {
                // Tail prefetch: kt+1's stage is resident after wait<1>
                // (only the group issued THIS iter remains outstanding).
                cp_wait<1>();
                loadFrag(cb ^ 1, aNx, bNx, 0);
            }
#pragma unroll
            for (int mi = 0; mi < 4; mi++)
#pragma unroll
                for (int nj = 0; nj < 8; nj++)
                    mma16816(acc[mi][nj], afr[cb][mi], bfr[cb][nj]);
        }

        stRead = stNext;
        stWrite = (stWrite == NSTAGES - 1) ? 0 : stWrite + 1;
    }
    cp_wait<0>();

    // ---- Epilogue ----
    const int groupRow = lane >> 2;
    const int colPair = (lane & 3) * 2;
#pragma unroll
    for (int mi = 0; mi < 4; mi++) {
        const int r0 = mBase + warp_m * 64 + mi * 16 + groupRow;
        const int r1 = r0 + 8;
        const float rs0 = g_rowsum[r0];
        const float rs1 = g_rowsum[r1];
        float* o0 = out + (size_t)r0 * N_DIM + nBase;
        float* o1 = out + (size_t)r1 * N_DIM + nBase;
#pragma unroll
        for (int nj = 0; nj < 8; nj++) {
            const int c = warp_n * 64 + nj * 8 + colPair;
            float2 v0, v1;
            v0.x = acc[mi][nj][0] * sS[c]     - rs0 * sZ[c]     + sBi[c];
            v0.y = acc[mi][nj][1] * sS[c + 1] - rs0 * sZ[c + 1] + sBi[c + 1];
            v1.x = acc[mi][nj][2] * sS[c]     - rs1 * sZ[c]     + sBi[c];
            v1.y = acc[mi][nj][3] * sS[c + 1] - rs1 * sZ[c + 1] + sBi[c + 1];
            *reinterpret_cast<float2*>(o0 + c) = v0;
            *reinterpret_cast<float2*>(o1 + c) = v1;
        }
    }
}

// ---------------------------------------------------------------------------
// Host
// ---------------------------------------------------------------------------
extern "C" void kernel_launch(void* const* d_in, const int* in_sizes, int n_in,
                              void* d_out, int out_size) {
    const float* x       = (const float*)d_in[0];
    const int*   qweight = (const int*)d_in[1];
    const float* scales  = (const float*)d_in[2];
    const int*   qzeros  = (const int*)d_in[3];
    const float* bias    = (const float*)d_in[4];
    float* out = (float*)d_out;

    cudaFuncSetAttribute(gemm_kernel, cudaFuncAttributeMaxDynamicSharedMemorySize,
                         SMEM_TOTAL);

    prep_kernel<<<UNPACK_BLOCKS + M_DIM, 256>>>(qweight, x);
    gemm_kernel<<<MT_TILES * NT_TILES, 128, SMEM_TOTAL>>>(scales, qzeros, bias, out);
}

// round 13
// speedup vs baseline: 1.0551x; 1.0456x over previous
#include <cuda_runtime.h>
#include <cuda_fp16.h>
#include <cstdint>

// ---------------------------------------------------------------------------
// Problem constants
// ---------------------------------------------------------------------------
#define K_DIM 4096
#define N_DIM 11008
#define M_DIM 8192
#define NGC   (N_DIM / 8)          // packed int32 per K row

// GEMM tiling
#define BM 128
#define BN 128
#define BK 64
#define KT (K_DIM / BK)            // 64 k-iterations
#define NSTAGES 3
#define STAGE_A_BYTES (BM * BK * 2)    // 16384
#define STAGE_B_BYTES (BN * BK * 2)    // 16384
#define SMEM_A 0
#define SMEM_B (NSTAGES * STAGE_A_BYTES)                  // 49152
#define SMEM_COEF (SMEM_B + NSTAGES * STAGE_B_BYTES)      // 98304
#define SMEM_TOTAL (SMEM_COEF + 3 * BN * 4)               // 99840

#define NT_TILES (N_DIM / BN)      // 86
#define MT_TILES (M_DIM / BM)      // 64
#define GROUP_M 8

#define UNPACK_BLOCKS ((N_DIM / 256) * (K_DIM / 64))   // 43 * 64 = 2752
#define NB_BLOCKS (N_DIM / 256)                        // 43

// ---------------------------------------------------------------------------
// Device scratch (no allocations allowed in kernel_launch)
// ---------------------------------------------------------------------------
__device__ __align__(1024) __half g_Wt[(size_t)N_DIM * K_DIM];   // W^T [N,K] fp16
__device__ __align__(1024) __half g_Xh[(size_t)M_DIM * K_DIM];   // X   [M,K] fp16
__device__ float g_rowsum[M_DIM];

// ---------------------------------------------------------------------------
// PTX helpers (generic sm_80-level PTX only: compiles under compute_103)
// ---------------------------------------------------------------------------
__device__ __forceinline__ uint32_t smem_u32(const void* p) {
    uint32_t a;
    asm("{ .reg .u64 t; cvta.to.shared.u64 t, %1; cvt.u32.u64 %0, t; }"
        : "=r"(a) : "l"(p));
    return a;
}

__device__ __forceinline__ void cp_async16(uint32_t dst, const void* src) {
    asm volatile("cp.async.cg.shared.global [%0], [%1], 16;"
                 :: "r"(dst), "l"(__cvta_generic_to_global(src)) : "memory");
}
__device__ __forceinline__ void cp_commit() {
    asm volatile("cp.async.commit_group;" ::: "memory");
}
template <int N>
__device__ __forceinline__ void cp_wait() {
    asm volatile("cp.async.wait_group %0;" :: "n"(N) : "memory");
}

__device__ __forceinline__ void ldsm_x4(uint32_t& r0, uint32_t& r1, uint32_t& r2,
                                        uint32_t& r3, uint32_t addr) {
    asm volatile("ldmatrix.sync.aligned.m8n8.x4.shared.b16 {%0,%1,%2,%3}, [%4];"
                 : "=r"(r0), "=r"(r1), "=r"(r2), "=r"(r3) : "r"(addr));
}

__device__ __forceinline__ void mma16816(float* c, const uint32_t* a, const uint32_t* b) {
    asm volatile(
        "mma.sync.aligned.m16n8k16.row.col.f32.f16.f16.f32 "
        "{%0,%1,%2,%3}, {%4,%5,%6,%7}, {%8,%9}, {%0,%1,%2,%3};"
        : "+f"(c[0]), "+f"(c[1]), "+f"(c[2]), "+f"(c[3])
        : "r"(a[0]), "r"(a[1]), "r"(a[2]), "r"(a[3]), "r"(b[0]), "r"(b[1]));
}

// ---------------------------------------------------------------------------
// Kernel 0 (fused prep): blocks [0, UNPACK_BLOCKS) unpack int4 weights ->
// g_Wt[N][K] fp16; blocks [UNPACK_BLOCKS, +M_DIM) convert X fp32 -> fp16 +
// rowsum of the rounded values. Independent work, overlapped on the chip.
// ---------------------------------------------------------------------------
__global__ __launch_bounds__(256) void prep_kernel(const int* __restrict__ qw,
                                                   const float* __restrict__ x) {
    __shared__ int w[64][32];          // 8KB (unpack branch only)
    __shared__ float ws[8];

    if (blockIdx.x < UNPACK_BLOCKS) {
        const int bx = blockIdx.x % NB_BLOCKS;
        const int by = blockIdx.x / NB_BLOCKS;
        const int n0 = bx * 256;
        const int k0 = by * 64;
        const int ngBase = n0 >> 3;
        const int lane = threadIdx.x & 31;
        const int wq = threadIdx.x >> 5;

#pragma unroll
        for (int i = 0; i < 8; i++) {
            const int k = wq * 8 + i;
            w[k][lane] = qw[(size_t)(k0 + k) * NGC + ngBase + lane];
        }
        __syncthreads();

        const int t = threadIdx.x;     // owns output row n0 + t
        const int col = t >> 3;
        const int sh = (t & 7) * 4;
        __half2 buf[32];
#pragma unroll
        for (int k = 0; k < 64; k += 2) {
            const uint32_t q0 = ((uint32_t)w[k][col] >> sh) & 0xF;
            const uint32_t q1 = ((uint32_t)w[k + 1][col] >> sh) & 0xF;
            buf[k >> 1] = __floats2half2_rn((float)q0, (float)q1);
        }
        uint4* dst = reinterpret_cast<uint4*>(g_Wt + (size_t)(n0 + t) * K_DIM + k0);
        const uint4* src = reinterpret_cast<const uint4*>(buf);
#pragma unroll
        for (int i = 0; i < 8; i++) dst[i] = src[i];
    } else {
        const int m = blockIdx.x - UNPACK_BLOCKS;
        const float4* xr = reinterpret_cast<const float4*>(x + (size_t)m * K_DIM);
        uint2* xo = reinterpret_cast<uint2*>(g_Xh + (size_t)m * K_DIM);
        float sum = 0.f;
#pragma unroll
        for (int i = 0; i < 4; i++) {
            const int j = threadIdx.x + i * 256;
            const float4 v = xr[j];
            __half2 a = __floats2half2_rn(v.x, v.y);
            __half2 b = __floats2half2_rn(v.z, v.w);
            uint2 u;
            u.x = *reinterpret_cast<uint32_t*>(&a);
            u.y = *reinterpret_cast<uint32_t*>(&b);
            xo[j] = u;
            const float2 fa = __half22float2(a);
            const float2 fb = __half22float2(b);
            sum += (fa.x + fa.y) + (fb.x + fb.y);
        }
#pragma unroll
        for (int off = 16; off; off >>= 1) sum += __shfl_xor_sync(0xffffffffu, sum, off);
        if ((threadIdx.x & 31) == 0) ws[threadIdx.x >> 5] = sum;
        __syncthreads();
        if (threadIdx.x == 0) {
            float s = 0.f;
#pragma unroll
            for (int wi = 0; wi < 8; wi++) s += ws[wi];
            g_rowsum[m] = s;
        }
    }
}

// ---------------------------------------------------------------------------
// Kernel 1: mma.sync fp16 GEMM, 128x128x64 CTA tile, four 64x64 warps, occ 2,
// 3-stage cp.async pipeline, one barrier per k-iter, persistent fragment
// double-buffer. HAND-INTERLEAVED mainloop: each k-iter = 16 sub-blocks of
// 8 HMMA; one next-slice ldmatrix after every sub-block, 2 cp.async chunks
// after each ks0/ks1 sub-block (single commit/iter, tail cp_wait<1>).
// Post-barrier instruction stream starts with pure HMMA.
// Epilogue: out = acc*scale - rowsum*scale*zp + bias
// ---------------------------------------------------------------------------
__global__ __launch_bounds__(128, 2) void gemm_kernel(
    const float* __restrict__ scales,
    const int*   __restrict__ qzeros,
    const float* __restrict__ bias,
    float* __restrict__ out)
{
    extern __shared__ char smem[];
    const uint32_t sb = smem_u32(smem);
    const int tid = threadIdx.x;
    const int lane = tid & 31;
    const int wid = tid >> 5;           // 0..3

    // CTA swizzle: GROUP_M m-tiles per group for L2 reuse
    const int pid = blockIdx.x;
    const int group = pid / (GROUP_M * NT_TILES);
    const int rem = pid - group * (GROUP_M * NT_TILES);
    const int mt = group * GROUP_M + (rem & (GROUP_M - 1));
    const int nt = rem >> 3;   // GROUP_M == 8
    const int mBase = mt * BM;
    const int nBase = nt * BN;

    // Epilogue coefficients (128 threads cover BN=128 exactly)
    float* sS = reinterpret_cast<float*>(smem + SMEM_COEF);
    float* sZ = sS + BN;
    float* sBi = sZ + BN;
    {
        const int n = nBase + tid;
        const float sc = scales[n];
        const int zq = qzeros[n >> 3];
        const int zp = (zq >> ((n & 7) * 4)) & 0xF;
        sS[tid] = sc;
        sZ[tid] = sc * (float)zp;
        sBi[tid] = bias[n];
    }

    // cp.async indices: 128 threads, 16B chunks; rows of 128B (8 chunks)
    const int ldRow = tid >> 3;          // 0..15
    const int ldChunk = tid & 7;         // 0..7
    const uint32_t swz = (uint32_t)((ldChunk ^ (ldRow & 7)) << 4);

    const __half* gA = g_Xh + (size_t)mBase * K_DIM;
    const __half* gB = g_Wt + (size_t)nBase * K_DIM;

    // Full-tile issue (prologue only)
    auto issue = [&](int st, int kt) {
        const int gk = kt * BK + ldChunk * 8;
#pragma unroll
        for (int i = 0; i < 8; i++) {
            const int row = ldRow + i * 16;
            cp_async16(sb + SMEM_A + st * STAGE_A_BYTES + row * 128 + swz,
                       gA + (size_t)row * K_DIM + gk);
        }
#pragma unroll
        for (int i = 0; i < 8; i++) {
            const int row = ldRow + i * 16;
            cp_async16(sb + SMEM_B + st * STAGE_B_BYTES + row * 128 + swz,
                       gB + (size_t)row * K_DIM + gk);
        }
    };

    // Warp tiling: 2 (m) x 2 (n) warps; warp tile 64 x 64
    const int warp_m = wid >> 1;         // 0..1
    const int warp_n = wid & 1;          // 0..1
    const int rowA0 = warp_m * 64 + (lane & 15);
    const int rowB0 = warp_n * 64 + (lane & 15);
    const int halfSel = lane >> 4;

    const uint32_t aAddrBase = sb + SMEM_A + rowA0 * 128;
    const uint32_t bAddrBase = sb + SMEM_B + rowB0 * 128;
    const uint32_t xorA = (uint32_t)(rowA0 & 7);
    const uint32_t xorB = (uint32_t)(rowB0 & 7);

    float acc[4][8][4];
#pragma unroll
    for (int mi = 0; mi < 4; mi++)
#pragma unroll
        for (int nj = 0; nj < 8; nj++)
#pragma unroll
            for (int e = 0; e < 4; e++) acc[mi][nj][e] = 0.f;

    uint32_t afr[2][4][4];
    uint32_t bfr[2][8][2];

    // Single-piece fragment loaders
    auto ldsmA1 = [&](int buf, uint32_t aSt, int ks, int mi) {
        const uint32_t c = (uint32_t)(ks * 2 + halfSel);
        ldsm_x4(afr[buf][mi][0], afr[buf][mi][1], afr[buf][mi][2],
                afr[buf][mi][3], aSt + mi * 16 * 128 + ((c ^ xorA) << 4));
    };
    auto ldsmB1 = [&](int buf, uint32_t bSt, int ks, int ni) {
        const uint32_t c = (uint32_t)(ks * 2 + halfSel);
        uint32_t r0, r1, r2, r3;
        ldsm_x4(r0, r1, r2, r3, bSt + ni * 16 * 128 + ((c ^ xorB) << 4));
        bfr[buf][ni * 2][0] = r0;     bfr[buf][ni * 2][1] = r2;
        bfr[buf][ni * 2 + 1][0] = r1; bfr[buf][ni * 2 + 1][1] = r3;
    };
    auto loadFragFull = [&](int buf, uint32_t aSt, uint32_t bSt, int ks) {
#pragma unroll
        for (int mi = 0; mi < 4; mi++) ldsmA1(buf, aSt, ks, mi);
#pragma unroll
        for (int ni = 0; ni < 4; ni++) ldsmB1(buf, bSt, ks, ni);
    };
    // One 16B chunk of the refill (i = 0..7 A, 8..15 B)
    auto chunk = [&](int st, int gk, int i) {
        if (i < 8) {
            const int row = ldRow + i * 16;
            cp_async16(sb + SMEM_A + st * STAGE_A_BYTES + row * 128 + swz,
                       gA + (size_t)row * K_DIM + gk);
        } else {
            const int row = ldRow + (i - 8) * 16;
            cp_async16(sb + SMEM_B + st * STAGE_B_BYTES + row * 128 + swz,
                       gB + (size_t)row * K_DIM + gk);
        }
    };
    auto mmaRow = [&](int cb, int mi) {
#pragma unroll
        for (int nj = 0; nj < 8; nj++)
            mma16816(acc[mi][nj], afr[cb][mi], bfr[cb][nj]);
    };

    // Prologue: fill stages 0 and 1; preload (kt=0, ks=0) fragments
    issue(0, 0); cp_commit();
    issue(1, 1); cp_commit();
    cp_wait<1>();
    __syncthreads();
    loadFragFull(0, aAddrBase, bAddrBase, 0);

    int stRead = 0;                      // stage holding k-iter kt
    int stWrite = NSTAGES - 1;           // stage to refill (= (kt+2)%3)

    for (int kt = 0; kt < KT; kt++) {
        __syncthreads();                 // all warps done reading stage stWrite

        const uint32_t aSt = aAddrBase + stRead * STAGE_A_BYTES;
        const uint32_t bSt = bAddrBase + stRead * STAGE_B_BYTES;
        const int stNext = (stRead == NSTAGES - 1) ? 0 : stRead + 1;
        const uint32_t aNx = aAddrBase + stNext * STAGE_A_BYTES;
        const uint32_t bNx = bAddrBase + stNext * STAGE_B_BYTES;
        const bool doIss = (kt + 2 < KT);
        const bool doTail = (kt + 1 < KT);
        const int gk = (kt + 2) * BK + ldChunk * 8;

        // ---- ks0: MMA(buf0) first (pure HMMA post-barrier); interleave
        //      ldsm of ks1->buf1 and A-refill chunks between sub-blocks.
#pragma unroll
        for (int mi = 0; mi < 4; mi++) {
            mmaRow(0, mi);
            ldsmA1(1, aSt, 1, mi);
            ldsmB1(1, bSt, 1, mi);
            if (doIss) { chunk(stWrite, gk, 2 * mi); chunk(stWrite, gk, 2 * mi + 1); }
        }
        // ---- ks1: MMA(buf1); ldsm ks2->buf0; B-refill chunks
#pragma unroll
        for (int mi = 0; mi < 4; mi++) {
            mmaRow(1, mi);
            ldsmA1(0, aSt, 2, mi);
            ldsmB1(0, bSt, 2, mi);
            if (doIss) { chunk(stWrite, gk, 8 + 2 * mi); chunk(stWrite, gk, 9 + 2 * mi); }
        }
        cp_commit();                     // one group per iter (possibly empty)
        // ---- ks2: MMA(buf0); ldsm ks3->buf1
#pragma unroll
        for (int mi = 0; mi < 4; mi++) {
            mmaRow(0, mi);
            ldsmA1(1, aSt, 3, mi);
            ldsmB1(1, bSt, 3, mi);
        }
        // ---- ks3: MMA(buf1); tail-prefetch next iter ks0 -> buf0
        mmaRow(1, 0);
        cp_wait<1>();                    // kt+1's stage resident (1 outstanding = this iter's group)
        if (doTail) { ldsmA1(0, aNx, 0, 0); ldsmB1(0, bNx, 0, 0); }
#pragma unroll
        for (int mi = 1; mi < 4; mi++) {
            mmaRow(1, mi);
            if (doTail) { ldsmA1(0, aNx, 0, mi); ldsmB1(0, bNx, 0, mi); }
        }

        stRead = stNext;
        stWrite = (stWrite == NSTAGES - 1) ? 0 : stWrite + 1;
    }
    cp_wait<0>();

    // ---- Epilogue ----
    const int groupRow = lane >> 2;
    const int colPair = (lane & 3) * 2;
#pragma unroll
    for (int mi = 0; mi < 4; mi++) {
        const int r0 = mBase + warp_m * 64 + mi * 16 + groupRow;
        const int r1 = r0 + 8;
        const float rs0 = g_rowsum[r0];
        const float rs1 = g_rowsum[r1];
        float* o0 = out + (size_t)r0 * N_DIM + nBase;
        float* o1 = out + (size_t)r1 * N_DIM + nBase;
#pragma unroll
        for (int nj = 0; nj < 8; nj++) {
            const int c = warp_n * 64 + nj * 8 + colPair;
            float2 v0, v1;
            v0.x = acc[mi][nj][0] * sS[c]     - rs0 * sZ[c]     + sBi[c];
            v0.y = acc[mi][nj][1] * sS[c + 1] - rs0 * sZ[c + 1] + sBi[c + 1];
            v1.x = acc[mi][nj][2] * sS[c]     - rs1 * sZ[c]     + sBi[c];
            v1.y = acc[mi][nj][3] * sS[c + 1] - rs1 * sZ[c + 1] + sBi[c + 1];
            *reinterpret_cast<float2*>(o0 + c) = v0;
            *reinterpret_cast<float2*>(o1 + c) = v1;
        }
    }
}

// ---------------------------------------------------------------------------
// Host
// ---------------------------------------------------------------------------
extern "C" void kernel_launch(void* const* d_in, const int* in_sizes, int n_in,
                              void* d_out, int out_size) {
    const float* x       = (const float*)d_in[0];
    const int*   qweight = (const int*)d_in[1];
    const float* scales  = (const float*)d_in[2];
    const int*   qzeros  = (const int*)d_in[3];
    const float* bias    = (const float*)d_in[4];
    float* out = (float*)d_out;

    cudaFuncSetAttribute(gemm_kernel, cudaFuncAttributeMaxDynamicSharedMemorySize,
                         SMEM_TOTAL);

    prep_kernel<<<UNPACK_BLOCKS + M_DIM, 256>>>(qweight, x);
    gemm_kernel<<<MT_TILES * NT_TILES, 128, SMEM_TOTAL>>>(scales, qzeros, bias, out);
}